// round 4
// baseline (speedup 1.0000x reference)
#include <cuda_runtime.h>

#define HH   48
#define HH2  2304
#define HH3  110592
#define NT   512
#define NEG_BIG (-3.402823466e38f)
#define SCF  0.35355339059327373f

__device__ __forceinline__ int PHY(int t) { return ((t >> 2) * 40) + ((t & 3) << 3); }

__device__ __forceinline__ float4 fmax4(float4 a, float4 b) {
    return make_float4(fmaxf(a.x,b.x), fmaxf(a.y,b.y), fmaxf(a.z,b.z), fmaxf(a.w,b.w));
}
__device__ __forceinline__ float hmax4(float4 a) {
    return fmaxf(fmaxf(a.x,a.y), fmaxf(a.z,a.w));
}

// CTA covers (b, head, wz, wy) and all NW windows along x.
// Pooled q/k/v layout: PHY(token)+c (4-token groups padded to 40 floats -> conflict-free
// transpose stores AND aligned float4 reads). so (attention out) reuses A c-major, stride 9X.
template<int BW, int SW, int NW, int SCALE>
__device__ __forceinline__ void do_scale(
    const float* __restrict__ q, const float* __restrict__ k,
    const float* __restrict__ v, const float* __restrict__ rpb,
    float* __restrict__ out, float* sm, int rem)
{
    constexpr int X    = 3*NW;
    constexpr int TOKS = 9*X;
    constexpr int GB   = ((TOKS + 3) / 4) * 40;
    constexpr int SO   = 9*X;
    const int tid = threadIdx.x;
    int wy = rem % NW; rem /= NW;
    int wz = rem % NW; rem /= NW;
    int head = rem & 1;
    int b    = rem >> 1;
    const int cb = (b*64 + (SCALE*2+head)*8) * HH3;

    float* bias27 = sm;            // 27*29 padded -> 784
    float* A  = sm + 784;
    float* Bm = A + GB;
    float* Cm = Bm + GB;
    float* sZ = Cm + GB;           // scatter z-interp (3456) / SW8 staging (6912)

    // ---- expanded bias table ----
    for (int u = tid; u < 729; u += NT) {
        int m = u / 27, n = u - m*27;
        int d0 = m/9 - n/9 + 2;
        int d1 = (m/3)%3 - (n/3)%3 + 2;
        int d2 = m%3 - n%3 + 2;
        bias27[m*29+n] = rpb[(d0*25 + d1*5 + d2)*2 + head];
    }

    // ---- pooling: c-inner lane mapping, conflict-free PHY stores ----
    if (SW == 1) {
        for (int u = tid; u < 864; u += NT) {
            int c = u & 7; int t2 = u >> 3; int xg = t2 % 12; int r = t2 / 12;
            int py = r % 3, pz = r / 3;
            int g = cb + c*HH3 + (wz*3+pz)*HH2 + (wy*3+py)*HH + xg*4;
            float4 aq = *(const float4*)(q+g);
            float4 ak = *(const float4*)(k+g);
            float4 av = *(const float4*)(v+g);
            int pb = (r*12 + xg)*40 + c;        // PHY(r*48+xg*4)+c, t&3==0
            A [pb]=aq.x; A [pb+8]=aq.y; A [pb+16]=aq.z; A [pb+24]=aq.w;
            Bm[pb]=ak.x; Bm[pb+8]=ak.y; Bm[pb+16]=ak.z; Bm[pb+24]=ak.w;
            Cm[pb]=av.x; Cm[pb+8]=av.y; Cm[pb+16]=av.z; Cm[pb+24]=av.w;
        }
    } else if (SW == 2) {
        for (int u = tid; u < 864; u += NT) {
            int c = u & 7; int t2 = u >> 3; int xg = t2 % 12; int r = t2 / 12;
            int py = r % 3, pz = r / 3;
            int z0 = wz*6 + pz*2, y0 = wy*6 + py*2;
            float4 mq = make_float4(NEG_BIG,NEG_BIG,NEG_BIG,NEG_BIG), mk = mq, mv = mq;
            #pragma unroll
            for (int dz = 0; dz < 2; dz++)
            #pragma unroll
            for (int dy = 0; dy < 2; dy++) {
                int g = cb + c*HH3 + (z0+dz)*HH2 + (y0+dy)*HH + xg*4;
                mq = fmax4(mq, *(const float4*)(q+g));
                mk = fmax4(mk, *(const float4*)(k+g));
                mv = fmax4(mv, *(const float4*)(v+g));
            }
            int t0 = r*24 + xg*2;
            int p0 = PHY(t0) + c, p1 = PHY(t0+1) + c;
            A [p0] = fmaxf(mq.x,mq.y); A [p1] = fmaxf(mq.z,mq.w);
            Bm[p0] = fmaxf(mk.x,mk.y); Bm[p1] = fmaxf(mk.z,mk.w);
            Cm[p0] = fmaxf(mv.x,mv.y); Cm[p1] = fmaxf(mv.z,mv.w);
        }
    } else if (SW == 4) {
        for (int u = tid; u < 864; u += NT) {
            int c = u & 7; int t2 = u >> 3; int px = t2 % 12; int r = t2 / 12;
            int py = r % 3, pz = r / 3;
            int z0 = wz*12 + pz*4, y0 = wy*12 + py*4;
            float4 mq = make_float4(NEG_BIG,NEG_BIG,NEG_BIG,NEG_BIG), mk = mq, mv = mq;
            #pragma unroll
            for (int dz = 0; dz < 4; dz++)
            #pragma unroll
            for (int dy = 0; dy < 4; dy++) {
                int g = cb + c*HH3 + (z0+dz)*HH2 + (y0+dy)*HH + px*4;
                mq = fmax4(mq, *(const float4*)(q+g));
                mk = fmax4(mk, *(const float4*)(k+g));
                mv = fmax4(mv, *(const float4*)(v+g));
            }
            int p = PHY(r*12 + px) + c;
            A[p] = hmax4(mq); Bm[p] = hmax4(mk); Cm[p] = hmax4(mv);
        }
    } else { // SW == 8: stage1 pools x,y coalesced; stage2 pools z
        float* sA0 = sZ; float* sA1 = sZ + 3456;
        for (int u = tid; u < 6912; u += NT) {
            int xg = u % 12; int t = u / 12; int c = t & 7; t >>= 3; int py = t % 3; int z = t / 3;
            int g = cb + c*HH3 + (wz*24+z)*HH2 + (wy*24+py*8)*HH + xg*4;
            float4 mq = *(const float4*)(q+g);
            float4 mk = *(const float4*)(k+g);
            #pragma unroll
            for (int dy = 1; dy < 8; dy++) {
                mq = fmax4(mq, *(const float4*)(q+g+dy*HH));
                mk = fmax4(mk, *(const float4*)(k+g+dy*HH));
            }
            float rq = hmax4(mq), rk = hmax4(mk);
            rq = fmaxf(rq, __shfl_xor_sync(0xffffffffu, rq, 1));
            rk = fmaxf(rk, __shfl_xor_sync(0xffffffffu, rk, 1));
            if (!(xg & 1)) {
                int s = ((z*3+py)*6 + (xg>>1))*8 + c;
                sA0[s] = rq; sA1[s] = rk;
            }
        }
        __syncthreads();
        for (int u = tid; u < 432; u += NT) {
            int c = u & 7; int t = u >> 3; int px = t % 6; t /= 6; int py = t % 3; int pz = t / 3;
            float rq = NEG_BIG, rk = NEG_BIG;
            #pragma unroll
            for (int j = 0; j < 8; j++) {
                int s = (((pz*8+j)*3+py)*6 + px)*8 + c;
                rq = fmaxf(rq, sA0[s]); rk = fmaxf(rk, sA1[s]);
            }
            int p = PHY((pz*3+py)*6 + px) + c;
            A[p] = rq; Bm[p] = rk;
        }
        __syncthreads();
        for (int u = tid; u < 6912; u += NT) {
            int xg = u % 12; int t = u / 12; int c = t & 7; t >>= 3; int py = t % 3; int z = t / 3;
            int g = cb + c*HH3 + (wz*24+z)*HH2 + (wy*24+py*8)*HH + xg*4;
            float4 mv = *(const float4*)(v+g);
            #pragma unroll
            for (int dy = 1; dy < 8; dy++) mv = fmax4(mv, *(const float4*)(v+g+dy*HH));
            float rv = hmax4(mv);
            rv = fmaxf(rv, __shfl_xor_sync(0xffffffffu, rv, 1));
            if (!(xg & 1)) sA0[((z*3+py)*6 + (xg>>1))*8 + c] = rv;
        }
        __syncthreads();
        for (int u = tid; u < 432; u += NT) {
            int c = u & 7; int t = u >> 3; int px = t % 6; t /= 6; int py = t % 3; int pz = t / 3;
            float rv = NEG_BIG;
            #pragma unroll
            for (int j = 0; j < 8; j++) rv = fmaxf(rv, sA0[(((pz*8+j)*3+py)*6 + px)*8 + c]);
            Cm[PHY((pz*3+py)*6 + px) + c] = rv;
        }
    }
    __syncthreads();

    // ---- attention: warp wid = window, lane = token m; two passes, low regs ----
    const int wid = tid >> 5, lane = tid & 31;
    const bool act = (wid < NW) && (lane < 27);
    float4 q0, q1;
    float rmax = NEG_BIG, rsum = 0.f;
    int tm = 0;
    if (act) {
        tm = ((lane/9)*3 + (lane/3)%3)*X + wid*3 + lane%3;
        int mp = PHY(tm);
        q0 = *(const float4*)(A + mp);
        q1 = *(const float4*)(A + mp + 4);
        // pass A: running max + sum (online)
        #pragma unroll
        for (int n = 0; n < 27; n++) {
            int t = ((n/9)*3 + (n/3)%3)*X + (n%3) + wid*3;
            int ph = PHY(t);
            float4 k0 = *(const float4*)(Bm+ph);
            float4 k1 = *(const float4*)(Bm+ph+4);
            float s = (q0.x*k0.x + q0.y*k0.y + q0.z*k0.z + q0.w*k0.w
                     + q1.x*k1.x + q1.y*k1.y + q1.z*k1.z + q1.w*k1.w) * SCF;
            float nm = fmaxf(rmax, s);
            rsum = rsum*__expf(rmax - nm) + __expf(s - nm);
            rmax = nm;
        }
    }
    __syncthreads();   // all q reads from A done before so overwrites A
    if (act) {
        float rs = 1.f / rsum;
        float o0=0,o1=0,o2=0,o3=0,o4=0,o5=0,o6=0,o7=0;
        #pragma unroll
        for (int n = 0; n < 27; n++) {
            int t = ((n/9)*3 + (n/3)%3)*X + (n%3) + wid*3;
            int ph = PHY(t);
            float4 k0 = *(const float4*)(Bm+ph);
            float4 k1 = *(const float4*)(Bm+ph+4);
            float s = (q0.x*k0.x + q0.y*k0.y + q0.z*k0.z + q0.w*k0.w
                     + q1.x*k1.x + q1.y*k1.y + q1.z*k1.z + q1.w*k1.w) * SCF;
            float w = __expf(s - rmax)*rs + bias27[lane*29 + n];
            float4 v0 = *(const float4*)(Cm+ph);
            float4 v1 = *(const float4*)(Cm+ph+4);
            o0 += w*v0.x; o1 += w*v0.y; o2 += w*v0.z; o3 += w*v0.w;
            o4 += w*v1.x; o5 += w*v1.y; o6 += w*v1.z; o7 += w*v1.w;
        }
        A[0*SO+tm]=o0; A[1*SO+tm]=o1; A[2*SO+tm]=o2; A[3*SO+tm]=o3;
        A[4*SO+tm]=o4; A[5*SO+tm]=o5; A[6*SO+tm]=o6; A[7*SO+tm]=o7;
    }
    __syncthreads();

    // ---- scatter ----
    if (SCALE == 0) {
        for (int u = tid; u < 864; u += NT) {
            int xg = u % 12; int t = u / 12; int py = t % 3; t /= 3; int pz = t % 3; int c = t / 3;
            float4 val = *(const float4*)(A + c*SO + (pz*3+py)*48 + xg*4);
            int g = cb + c*HH3 + (wz*3+pz)*HH2 + (wy*3+py)*HH + xg*4;
            *(float4*)(out+g) = val;
        }
    } else {
        for (int u = tid; u < 3456; u += NT) {   // 8*BW*3*X == 3456 for all scales
            int px = u % X; int t = u / X; int py = t % 3; t /= 3; int oz = t % BW; int c = t / BW;
            int iz = (2*oz >= BW-1) ? 1 : 0;
            float wzf = (float)(oz*2) / (float)(BW-1) - (float)iz;
            float a0 = A[c*SO + (iz*3+py)*X + px];
            float a1 = A[c*SO + ((iz+1)*3+py)*X + px];
            sZ[((c*BW+oz)*3+py)*X + px] = a0 + wzf*(a1-a0);
        }
        __syncthreads();
        constexpr int VEC = (BW == 6) ? 2 : 4;
        constexpr int NXG = 48/VEC;
        constexpr int ITEMS = 8*BW*BW*NXG;
        for (int u = tid; u < ITEMS; u += NT) {
            int xg = u % NXG; int t = u / NXG; int oy = t % BW; t /= BW; int oz = t % BW; int c = t / BW;
            int x0 = xg*VEC;
            int win = x0 / BW; int lx0 = x0 - win*BW;
            int iy = (2*oy >= BW-1) ? 1 : 0;
            float wyf = (float)(oy*2) / (float)(BW-1) - (float)iy;
            const float* z0 = sZ + ((c*BW+oz)*3+iy)*X + win*3;
            const float* z1 = z0 + X;
            float b0 = z0[0] + wyf*(z1[0]-z0[0]);
            float b1 = z0[1] + wyf*(z1[1]-z0[1]);
            float b2 = z0[2] + wyf*(z1[2]-z0[2]);
            float res[VEC];
            #pragma unroll
            for (int e = 0; e < VEC; e++) {
                int lx = lx0 + e;
                int il = (2*lx >= BW-1) ? 1 : 0;
                float wl = (float)(lx*2) / (float)(BW-1) - (float)il;
                float lo = il ? b1 : b0;
                float hi = il ? b2 : b1;
                res[e] = lo + wl*(hi-lo);
            }
            int g = cb + c*HH3 + (wz*BW+oz)*HH2 + (wy*BW+oy)*HH + x0;
            if (VEC == 4) *(float4*)(out+g) = make_float4(res[0],res[1],res[2],res[3]);
            else          *(float2*)(out+g) = make_float2(res[0],res[1]);
        }
    }
}

// Grid (heavy scales first):
//   [0,32)      scale 3: bw=24 sw=8  NW=2
//   [32,160)    scale 2: bw=12 sw=4  NW=4
//   [160,672)   scale 1: bw=6  sw=2  NW=8
//   [672,2720)  scale 0: bw=3  sw=1  NW=16
__global__ void __launch_bounds__(NT, 3)
pwa_kernel(const float* __restrict__ q, const float* __restrict__ k,
           const float* __restrict__ v, const float* __restrict__ rpb,
           float* __restrict__ out)
{
    extern __shared__ float sm[];
    int bid = blockIdx.x;
    if (bid < 32)        do_scale<24, 8, 2,  3>(q, k, v, rpb, out, sm, bid);
    else if (bid < 160)  do_scale<12, 4, 4,  2>(q, k, v, rpb, out, sm, bid - 32);
    else if (bid < 672)  do_scale< 6, 2, 8,  1>(q, k, v, rpb, out, sm, bid - 160);
    else                 do_scale< 3, 1, 16, 0>(q, k, v, rpb, out, sm, bid - 672);
}

#define SMEM_BYTES ((784 + 3*4320) * 4)   // 54,976 B (scale-0 worst case)

extern "C" void kernel_launch(void* const* d_in, const int* in_sizes, int n_in,
                              void* d_out, int out_size)
{
    const float* q   = (const float*)d_in[0];
    const float* k   = (const float*)d_in[1];
    const float* v   = (const float*)d_in[2];
    const float* rpb = (const float*)d_in[3];
    cudaFuncSetAttribute(pwa_kernel, cudaFuncAttributeMaxDynamicSharedMemorySize, SMEM_BYTES);
    pwa_kernel<<<2720, NT, SMEM_BYTES>>>(q, k, v, rpb, (float*)d_out);
}

// round 5
// speedup vs baseline: 1.1216x; 1.1216x over previous
#include <cuda_runtime.h>

#define HH   48
#define HH2  2304
#define HH3  110592
#define NT   512
#define NEG_BIG (-3.402823466e38f)
#define SCF  0.35355339059327373f

__device__ __forceinline__ int PHY(int t) { return ((t >> 2) * 40) + ((t & 3) << 3); }

__device__ __forceinline__ float4 fmax4(float4 a, float4 b) {
    return make_float4(fmaxf(a.x,b.x), fmaxf(a.y,b.y), fmaxf(a.z,b.z), fmaxf(a.w,b.w));
}
__device__ __forceinline__ float hmax4(float4 a) {
    return fmaxf(fmaxf(a.x,a.y), fmaxf(a.z,a.w));
}

// CTA covers (b, head, wz, wy) and all NW windows along x.
// Pooled q/k/v layout: PHY(token)+c — 4-token groups padded 32->40 floats:
// conflict-free transpose stores AND 16B-aligned float4 reads.
// Attention output reuses A, c-major, stride SO = 9X.
template<int BW, int SW, int NW, int SCALE>
__device__ __forceinline__ void do_scale(
    const float* __restrict__ q, const float* __restrict__ k,
    const float* __restrict__ v, const float* __restrict__ rpb,
    float* __restrict__ out, float* sm, int rem)
{
    constexpr int X    = 3*NW;
    constexpr int TOKS = 9*X;
    constexpr int GB   = ((TOKS + 3) / 4) * 40;
    constexpr int SO   = 9*X;
    const int tid = threadIdx.x;
    int wy = rem % NW; rem /= NW;
    int wz = rem % NW; rem /= NW;
    int head = rem & 1;
    int b    = rem >> 1;
    const int cb = (b*64 + (SCALE*2+head)*8) * HH3;

    float* bias27 = sm;            // 27*29 padded -> 784
    float* A  = sm + 784;
    float* Bm = A + GB;
    float* Cm = Bm + GB;
    float* sZ = Cm + GB;           // scatter z-interp (3456) / SW8 staging (6912)

    // ---- expanded bias table ----
    for (int u = tid; u < 729; u += NT) {
        int m = u / 27, n = u - m*27;
        int d0 = m/9 - n/9 + 2;
        int d1 = (m/3)%3 - (n/3)%3 + 2;
        int d2 = m%3 - n%3 + 2;
        bias27[m*29+n] = rpb[(d0*25 + d1*5 + d2)*2 + head];
    }

    // ---- pooling: c-inner lane mapping, conflict-free PHY stores ----
    if (SW == 1) {
        for (int u = tid; u < 864; u += NT) {
            int c = u & 7; int t2 = u >> 3; int xg = t2 % 12; int r = t2 / 12;
            int py = r % 3, pz = r / 3;
            int g = cb + c*HH3 + (wz*3+pz)*HH2 + (wy*3+py)*HH + xg*4;
            float4 aq = *(const float4*)(q+g);
            float4 ak = *(const float4*)(k+g);
            float4 av = *(const float4*)(v+g);
            int pb = (r*12 + xg)*40 + c;        // PHY(r*48+xg*4)+c, t&3==0
            A [pb]=aq.x; A [pb+8]=aq.y; A [pb+16]=aq.z; A [pb+24]=aq.w;
            Bm[pb]=ak.x; Bm[pb+8]=ak.y; Bm[pb+16]=ak.z; Bm[pb+24]=ak.w;
            Cm[pb]=av.x; Cm[pb+8]=av.y; Cm[pb+16]=av.z; Cm[pb+24]=av.w;
        }
    } else if (SW == 2) {
        for (int u = tid; u < 864; u += NT) {
            int c = u & 7; int t2 = u >> 3; int xg = t2 % 12; int r = t2 / 12;
            int py = r % 3, pz = r / 3;
            int z0 = wz*6 + pz*2, y0 = wy*6 + py*2;
            float4 mq = make_float4(NEG_BIG,NEG_BIG,NEG_BIG,NEG_BIG), mk = mq, mv = mq;
            #pragma unroll
            for (int dz = 0; dz < 2; dz++)
            #pragma unroll
            for (int dy = 0; dy < 2; dy++) {
                int g = cb + c*HH3 + (z0+dz)*HH2 + (y0+dy)*HH + xg*4;
                mq = fmax4(mq, *(const float4*)(q+g));
                mk = fmax4(mk, *(const float4*)(k+g));
                mv = fmax4(mv, *(const float4*)(v+g));
            }
            int t0 = r*24 + xg*2;
            int p0 = PHY(t0) + c, p1 = PHY(t0+1) + c;
            A [p0] = fmaxf(mq.x,mq.y); A [p1] = fmaxf(mq.z,mq.w);
            Bm[p0] = fmaxf(mk.x,mk.y); Bm[p1] = fmaxf(mk.z,mk.w);
            Cm[p0] = fmaxf(mv.x,mv.y); Cm[p1] = fmaxf(mv.z,mv.w);
        }
    } else if (SW == 4) {
        for (int u = tid; u < 864; u += NT) {
            int c = u & 7; int t2 = u >> 3; int px = t2 % 12; int r = t2 / 12;
            int py = r % 3, pz = r / 3;
            int z0 = wz*12 + pz*4, y0 = wy*12 + py*4;
            float4 mq = make_float4(NEG_BIG,NEG_BIG,NEG_BIG,NEG_BIG), mk = mq, mv = mq;
            #pragma unroll
            for (int dz = 0; dz < 4; dz++)
            #pragma unroll
            for (int dy = 0; dy < 4; dy++) {
                int g = cb + c*HH3 + (z0+dz)*HH2 + (y0+dy)*HH + px*4;
                mq = fmax4(mq, *(const float4*)(q+g));
                mk = fmax4(mk, *(const float4*)(k+g));
                mv = fmax4(mv, *(const float4*)(v+g));
            }
            int p = PHY(r*12 + px) + c;
            A[p] = hmax4(mq); Bm[p] = hmax4(mk); Cm[p] = hmax4(mv);
        }
    } else { // SW == 8: stage1 pools x,y coalesced; stage2 pools z
        float* sA0 = sZ; float* sA1 = sZ + 3456;
        for (int u = tid; u < 6912; u += NT) {
            int xg = u % 12; int t = u / 12; int c = t & 7; t >>= 3; int py = t % 3; int z = t / 3;
            int g = cb + c*HH3 + (wz*24+z)*HH2 + (wy*24+py*8)*HH + xg*4;
            float4 mq = *(const float4*)(q+g);
            float4 mk = *(const float4*)(k+g);
            #pragma unroll
            for (int dy = 1; dy < 8; dy++) {
                mq = fmax4(mq, *(const float4*)(q+g+dy*HH));
                mk = fmax4(mk, *(const float4*)(k+g+dy*HH));
            }
            float rq = hmax4(mq), rk = hmax4(mk);
            rq = fmaxf(rq, __shfl_xor_sync(0xffffffffu, rq, 1));
            rk = fmaxf(rk, __shfl_xor_sync(0xffffffffu, rk, 1));
            if (!(xg & 1)) {
                int s = ((z*3+py)*6 + (xg>>1))*8 + c;
                sA0[s] = rq; sA1[s] = rk;
            }
        }
        __syncthreads();
        for (int u = tid; u < 432; u += NT) {
            int c = u & 7; int t = u >> 3; int px = t % 6; t /= 6; int py = t % 3; int pz = t / 3;
            float rq = NEG_BIG, rk = NEG_BIG;
            #pragma unroll
            for (int j = 0; j < 8; j++) {
                int s = (((pz*8+j)*3+py)*6 + px)*8 + c;
                rq = fmaxf(rq, sA0[s]); rk = fmaxf(rk, sA1[s]);
            }
            int p = PHY((pz*3+py)*6 + px) + c;
            A[p] = rq; Bm[p] = rk;
        }
        __syncthreads();
        for (int u = tid; u < 6912; u += NT) {
            int xg = u % 12; int t = u / 12; int c = t & 7; t >>= 3; int py = t % 3; int z = t / 3;
            int g = cb + c*HH3 + (wz*24+z)*HH2 + (wy*24+py*8)*HH + xg*4;
            float4 mv = *(const float4*)(v+g);
            #pragma unroll
            for (int dy = 1; dy < 8; dy++) mv = fmax4(mv, *(const float4*)(v+g+dy*HH));
            float rv = hmax4(mv);
            rv = fmaxf(rv, __shfl_xor_sync(0xffffffffu, rv, 1));
            if (!(xg & 1)) sA0[((z*3+py)*6 + (xg>>1))*8 + c] = rv;
        }
        __syncthreads();
        for (int u = tid; u < 432; u += NT) {
            int c = u & 7; int t = u >> 3; int px = t % 6; t /= 6; int py = t % 3; int pz = t / 3;
            float rv = NEG_BIG;
            #pragma unroll
            for (int j = 0; j < 8; j++) rv = fmaxf(rv, sA0[(((pz*8+j)*3+py)*6 + px)*8 + c]);
            Cm[PHY((pz*3+py)*6 + px) + c] = rv;
        }
    }
    __syncthreads();

    // ---- attention: warp wid = window, lane = token m; ONE pass, weights in regs ----
    const int wid = tid >> 5, lane = tid & 31;
    const bool act = (wid < NW) && (lane < 27);
    float w27[27];
    int tm = 0;
    if (act) {
        tm = ((lane/9)*3 + (lane/3)%3)*X + wid*3 + lane%3;
        int mp = PHY(tm);
        float4 q0 = *(const float4*)(A + mp);
        float4 q1 = *(const float4*)(A + mp + 4);
        float smax = NEG_BIG;
        #pragma unroll
        for (int n = 0; n < 27; n++) {
            int t = ((n/9)*3 + (n/3)%3)*X + (n%3) + wid*3;
            int ph = PHY(t);
            float4 k0 = *(const float4*)(Bm+ph);
            float4 k1 = *(const float4*)(Bm+ph+4);
            float s = (q0.x*k0.x + q0.y*k0.y + q0.z*k0.z + q0.w*k0.w
                     + q1.x*k1.x + q1.y*k1.y + q1.z*k1.z + q1.w*k1.w) * SCF;
            w27[n] = s;
            smax = fmaxf(smax, s);
        }
        float ssum = 0.f;
        #pragma unroll
        for (int n = 0; n < 27; n++) { float e = __expf(w27[n]-smax); w27[n] = e; ssum += e; }
        float rs = 1.f/ssum;
        #pragma unroll
        for (int n = 0; n < 27; n++) w27[n] = w27[n]*rs + bias27[lane*29+n];
    }
    __syncthreads();   // all q reads from A done before so overwrites A
    if (act) {
        float o0=0,o1=0,o2=0,o3=0,o4=0,o5=0,o6=0,o7=0;
        #pragma unroll
        for (int n = 0; n < 27; n++) {
            int t = ((n/9)*3 + (n/3)%3)*X + (n%3) + wid*3;
            int ph = PHY(t);
            float4 v0 = *(const float4*)(Cm+ph);
            float4 v1 = *(const float4*)(Cm+ph+4);
            float wn = w27[n];
            o0 += wn*v0.x; o1 += wn*v0.y; o2 += wn*v0.z; o3 += wn*v0.w;
            o4 += wn*v1.x; o5 += wn*v1.y; o6 += wn*v1.z; o7 += wn*v1.w;
        }
        A[0*SO+tm]=o0; A[1*SO+tm]=o1; A[2*SO+tm]=o2; A[3*SO+tm]=o3;
        A[4*SO+tm]=o4; A[5*SO+tm]=o5; A[6*SO+tm]=o6; A[7*SO+tm]=o7;
    }
    __syncthreads();

    // ---- scatter ----
    if (SCALE == 0) {
        for (int u = tid; u < 864; u += NT) {
            int xg = u % 12; int t = u / 12; int py = t % 3; t /= 3; int pz = t % 3; int c = t / 3;
            float4 val = *(const float4*)(A + c*SO + (pz*3+py)*48 + xg*4);
            int g = cb + c*HH3 + (wz*3+pz)*HH2 + (wy*3+py)*HH + xg*4;
            *(float4*)(out+g) = val;
        }
    } else {
        for (int u = tid; u < 3456; u += NT) {   // 8*BW*3*X == 3456 for all scales
            int px = u % X; int t = u / X; int py = t % 3; t /= 3; int oz = t % BW; int c = t / BW;
            int iz = (2*oz >= BW-1) ? 1 : 0;
            float wzf = (float)(oz*2) / (float)(BW-1) - (float)iz;
            float a0 = A[c*SO + (iz*3+py)*X + px];
            float a1 = A[c*SO + ((iz+1)*3+py)*X + px];
            sZ[((c*BW+oz)*3+py)*X + px] = a0 + wzf*(a1-a0);
        }
        __syncthreads();
        constexpr int VEC = (BW == 6) ? 2 : 4;
        constexpr int NXG = 48/VEC;
        constexpr int ITEMS = 8*BW*BW*NXG;
        for (int u = tid; u < ITEMS; u += NT) {
            int xg = u % NXG; int t = u / NXG; int oy = t % BW; t /= BW; int oz = t % BW; int c = t / BW;
            int x0 = xg*VEC;
            int win = x0 / BW; int lx0 = x0 - win*BW;
            int iy = (2*oy >= BW-1) ? 1 : 0;
            float wyf = (float)(oy*2) / (float)(BW-1) - (float)iy;
            const float* z0 = sZ + ((c*BW+oz)*3+iy)*X + win*3;
            const float* z1 = z0 + X;
            float b0 = z0[0] + wyf*(z1[0]-z0[0]);
            float b1 = z0[1] + wyf*(z1[1]-z0[1]);
            float b2 = z0[2] + wyf*(z1[2]-z0[2]);
            float res[VEC];
            #pragma unroll
            for (int e = 0; e < VEC; e++) {
                int lx = lx0 + e;
                int il = (2*lx >= BW-1) ? 1 : 0;
                float wl = (float)(lx*2) / (float)(BW-1) - (float)il;
                float lo = il ? b1 : b0;
                float hi = il ? b2 : b1;
                res[e] = lo + wl*(hi-lo);
            }
            int g = cb + c*HH3 + (wz*BW+oz)*HH2 + (wy*BW+oy)*HH + x0;
            if (VEC == 4) *(float4*)(out+g) = make_float4(res[0],res[1],res[2],res[3]);
            else          *(float2*)(out+g) = make_float2(res[0],res[1]);
        }
    }
}

// Grid (heavy scales first):
//   [0,32)      scale 3: bw=24 sw=8  NW=2
//   [32,160)    scale 2: bw=12 sw=4  NW=4
//   [160,672)   scale 1: bw=6  sw=2  NW=8
//   [672,2720)  scale 0: bw=3  sw=1  NW=16
__global__ void __launch_bounds__(NT)
pwa_kernel(const float* __restrict__ q, const float* __restrict__ k,
           const float* __restrict__ v, const float* __restrict__ rpb,
           float* __restrict__ out)
{
    extern __shared__ float sm[];
    int bid = blockIdx.x;
    if (bid < 32)        do_scale<24, 8, 2,  3>(q, k, v, rpb, out, sm, bid);
    else if (bid < 160)  do_scale<12, 4, 4,  2>(q, k, v, rpb, out, sm, bid - 32);
    else if (bid < 672)  do_scale< 6, 2, 8,  1>(q, k, v, rpb, out, sm, bid - 160);
    else                 do_scale< 3, 1, 16, 0>(q, k, v, rpb, out, sm, bid - 672);
}

#define SMEM_BYTES ((784 + 3*4320) * 4)   // 54,976 B (scale-0 worst case)

extern "C" void kernel_launch(void* const* d_in, const int* in_sizes, int n_in,
                              void* d_out, int out_size)
{
    const float* q   = (const float*)d_in[0];
    const float* k   = (const float*)d_in[1];
    const float* v   = (const float*)d_in[2];
    const float* rpb = (const float*)d_in[3];
    cudaFuncSetAttribute(pwa_kernel, cudaFuncAttributeMaxDynamicSharedMemorySize, SMEM_BYTES);
    pwa_kernel<<<2720, NT, SMEM_BYTES>>>(q, k, v, rpb, (float*)d_out);
}